// round 16
// baseline (speedup 1.0000x reference)
#include <cuda_runtime.h>
#include <cuda_fp16.h>
#include <cstdint>

#define BATCH 8192
#define IN_F  2048
#define OUT_F 2048
#define QB    7.0f
#define EPSF  1e-5f

// ---------------- scratch (static device arrays; no cudaMalloc) -------------
__device__ __half g_xq[(size_t)BATCH * IN_F];    // 32 MB quantized activations
__device__ __half g_wbin[(size_t)OUT_F * IN_F];  // 8 MB  sign weights
__device__ float  g_beta[OUT_F];
__device__ float  g_rs[BATCH];
__device__ int    g_ctr;                          // persistent-tile counter

// ---------------- fused prep: register-resident rows ------------------------
__global__ __launch_bounds__(256) void prep_kernel(const float* __restrict__ x,
                                                   const float* __restrict__ w) {
    const int tid = threadIdx.x, lane = tid & 31, wid = tid >> 5;
    __shared__ float red[3][8];
    if (blockIdx.x == 0 && tid == 0) g_ctr = 0;   // reset tile counter

    float v[8];
    if (blockIdx.x < 2048) {
        const int o = blockIdx.x;
        const float4* row = (const float4*)(w + (size_t)o * IN_F) + tid * 2;
        float4 p0 = row[0], p1 = row[1];
        v[0]=p0.x; v[1]=p0.y; v[2]=p0.z; v[3]=p0.w;
        v[4]=p1.x; v[5]=p1.y; v[6]=p1.z; v[7]=p1.w;

        float s0 = 0.f, s1 = 0.f;
        #pragma unroll
        for (int i = 0; i < 8; i++) { s0 += v[i]; s1 += fabsf(v[i]); }
        #pragma unroll
        for (int off = 16; off; off >>= 1) {
            s0 += __shfl_xor_sync(0xffffffffu, s0, off);
            s1 += __shfl_xor_sync(0xffffffffu, s1, off);
        }
        if (lane == 0) { red[0][wid] = s0; red[1][wid] = s1; }
        __syncthreads();
        float t0 = 0.f, t1 = 0.f;
        #pragma unroll
        for (int i = 0; i < 8; i++) { t0 += red[0][i]; t1 += red[1][i]; }
        float mean = t0 * (1.0f / IN_F);
        if (tid == 0) g_beta[o] = t1 * (1.0f / IN_F);

        __half h[8];
        #pragma unroll
        for (int i = 0; i < 8; i++) {
            float c = v[i] - mean;
            h[i] = __float2half_rn((c > 0.f) ? 1.0f : ((c < 0.f) ? -1.0f : 0.0f));
        }
        *((uint4*)(g_wbin + (size_t)o * IN_F) + tid) = *(const uint4*)h;
    } else {
        const int b = blockIdx.x - 2048;
        const float4* row = (const float4*)(x + (size_t)b * IN_F) + tid * 2;
        float4 p0 = row[0], p1 = row[1];
        v[0]=p0.x; v[1]=p0.y; v[2]=p0.z; v[3]=p0.w;
        v[4]=p1.x; v[5]=p1.y; v[6]=p1.z; v[7]=p1.w;

        float s0 = 0.f, s1 = 0.f;
        #pragma unroll
        for (int i = 0; i < 8; i++) { s0 += v[i]; s1 += v[i] * v[i]; }
        #pragma unroll
        for (int off = 16; off; off >>= 1) {
            s0 += __shfl_xor_sync(0xffffffffu, s0, off);
            s1 += __shfl_xor_sync(0xffffffffu, s1, off);
        }
        if (lane == 0) { red[0][wid] = s0; red[1][wid] = s1; }
        __syncthreads();
        float t0 = 0.f, t1 = 0.f;
        #pragma unroll
        for (int i = 0; i < 8; i++) { t0 += red[0][i]; t1 += red[1][i]; }
        float mu   = t0 * (1.0f / IN_F);
        float var  = t1 * (1.0f / IN_F) - mu * mu;
        float rstd = rsqrtf(var + EPSF);

        float lm = 0.f;
        #pragma unroll
        for (int i = 0; i < 8; i++) lm = fmaxf(lm, fabsf(v[i] - mu));
        #pragma unroll
        for (int off = 16; off; off >>= 1)
            lm = fmaxf(lm, __shfl_xor_sync(0xffffffffu, lm, off));
        if (lane == 0) red[2][wid] = lm;
        __syncthreads();
        float mx = 0.f;
        #pragma unroll
        for (int i = 0; i < 8; i++) mx = fmaxf(mx, red[2][i]);
        float gama = fmaxf(mx * rstd, EPSF);
        float s = rstd * (QB / gama);
        const float clo = -QB + EPSF, chi = QB - EPSF;

        __half h[8];
        #pragma unroll
        for (int i = 0; i < 8; i++) {
            float q = (v[i] - mu) * s;
            h[i] = __float2half_rn(fminf(fmaxf(q, clo), chi));
        }
        *((uint4*)(g_xq + (size_t)b * IN_F) + tid) = *(const uint4*)h;
        if (tid == 0) g_rs[b] = gama * (1.0f / QB);
    }
    cudaTriggerProgrammaticLaunchCompletion();
}

// ---------------- GEMM: persistent 256x128 tiles, 4-stage mbarrier ring ----
#define BM 256
#define BN 128
#define BK 64
#define SST 72            // smem row stride in halves (144B rows, conflict-free)
#define NSTG 4
#define NTHR 512
#define NTILES 512        // (8192/256) * (2048/128)

__device__ __forceinline__ void mma_f16(float* c, const uint32_t* a, const uint32_t* b) {
    asm volatile(
        "mma.sync.aligned.m16n8k16.row.col.f32.f16.f16.f32 "
        "{%0,%1,%2,%3}, {%4,%5,%6,%7}, {%8,%9}, {%0,%1,%2,%3};\n"
        : "+f"(c[0]), "+f"(c[1]), "+f"(c[2]), "+f"(c[3])
        : "r"(a[0]), "r"(a[1]), "r"(a[2]), "r"(a[3]), "r"(b[0]), "r"(b[1]));
}

__device__ __forceinline__ void ldsm4(uint32_t* r, uint32_t addr) {
    asm volatile("ldmatrix.sync.aligned.m8n8.x4.shared.b16 {%0,%1,%2,%3}, [%4];\n"
                 : "=r"(r[0]), "=r"(r[1]), "=r"(r[2]), "=r"(r[3]) : "r"(addr));
}

__device__ __forceinline__ void cpa16(uint32_t d, const void* s) {
    asm volatile("cp.async.cg.shared.global [%0], [%1], 16;\n" :: "r"(d), "l"(s));
}
__device__ __forceinline__ void mbar_init(uint32_t a, uint32_t cnt) {
    asm volatile("mbarrier.init.shared.b64 [%0], %1;" :: "r"(a), "r"(cnt) : "memory");
}
__device__ __forceinline__ void mbar_arrive(uint32_t a) {
    asm volatile("mbarrier.arrive.shared.b64 _, [%0];" :: "r"(a) : "memory");
}
__device__ __forceinline__ void cpa_mbar_arrive_noinc(uint32_t a) {
    asm volatile("cp.async.mbarrier.arrive.noinc.shared.b64 [%0];" :: "r"(a) : "memory");
}
__device__ __forceinline__ void mbar_wait(uint32_t a, uint32_t parity) {
    asm volatile(
        "{\n\t.reg .pred P;\n\t"
        "LW%=:\n\t"
        "mbarrier.try_wait.parity.acquire.cta.shared::cta.b64 P, [%0], %1, 0x989680;\n\t"
        "@P bra LD%=;\n\t"
        "bra LW%=;\n\t"
        "LD%=:\n\t}"
        :: "r"(a), "r"(parity) : "memory");
}

__global__ __launch_bounds__(NTHR, 1) void gemm_kernel(const float* __restrict__ bias,
                                                       float* __restrict__ out) {
    extern __shared__ __half sm[];
    // bytes [0,32): full[4]; [32,64): empty[4]; [64,72): tile mailbox x2;
    // [72,76): seq; tiles start at half-offset 64 (byte 128)
    __half* sA = sm + 64;                        // NSTG * BM * SST halves
    __half* sB = sm + 64 + NSTG * BM * SST;      // NSTG * BN * SST halves
    char* smc = (char*)sm;
    volatile int* shT  = (volatile int*)(smc + 64);
    volatile int* shSq = (volatile int*)(smc + 72);
    const uint32_t mbarBase = (uint32_t)__cvta_generic_to_shared(sm);
    const uint32_t fullM  = mbarBase;            // + 8*s
    const uint32_t emptyM = mbarBase + 32;       // + 8*s

    const int tid = threadIdx.x;
    const int lane = tid & 31, w = tid >> 5;
    const int wm = w >> 2, wn = w & 3;           // 4x4 warp grid, warp tile 64x32
    const int warp_m = wm * 64, warp_n = wn * 32;

    const uint32_t baseA = (uint32_t)__cvta_generic_to_shared(sA);
    const uint32_t baseB = (uint32_t)__cvta_generic_to_shared(sB);

    const __half* __restrict__ Aq = g_xq;
    const __half* __restrict__ Bw = g_wbin;

    const int matA = lane >> 3, ra = lane & 7;
    const int a_row_off = (matA & 1) * 8 + ra;
    const int a_col_off = (matA >> 1) * 8;
    const int b_n_off   = ((matA >> 1) ? 8 : 0) + ra;
    const int b_k_off   = (matA & 1) * 8;

    uint32_t aRow[4], bRow[2];
    #pragma unroll
    for (int mt = 0; mt < 4; ++mt)
        aRow[mt] = baseA + (uint32_t)((warp_m + mt * 16 + a_row_off) * SST + a_col_off) * 2;
    #pragma unroll
    for (int p = 0; p < 2; ++p)
        bRow[p] = baseB + (uint32_t)((warp_n + p * 16 + b_n_off) * SST + b_k_off) * 2;

    if (tid == 0) {
        #pragma unroll
        for (int s = 0; s < NSTG; s++) {
            mbar_init(fullM + 8 * s, NTHR);
            mbar_init(emptyM + 8 * s, 16);
        }
        *shSq = 0;
    }
    __syncthreads();
    cudaGridDependencySynchronize();

    // loader for tile at (m0,n0), ktile kt, into stage buf
    auto load_tile = [&](int m0, int n0, int kt, int buf) {
        const int k0 = kt * BK;
        #pragma unroll
        for (int i = 0; i < 4; i++) {            // A: 2048 chunks
            int c = tid + i * NTHR;
            int r = c >> 3, kc = c & 7;
            uint32_t doff = (uint32_t)((buf * BM * SST + r * SST + kc * 8) * 2);
            cpa16(baseA + doff, Aq + (size_t)(m0 + r) * IN_F + k0 + kc * 8);
        }
        #pragma unroll
        for (int i = 0; i < 2; i++) {            // B: 1024 chunks
            int c = tid + i * NTHR;
            int r = c >> 3, kc = c & 7;
            uint32_t doff = (uint32_t)((buf * BN * SST + r * SST + kc * 8) * 2);
            cpa16(baseB + doff, Bw + (size_t)(n0 + r) * IN_F + k0 + kc * 8);
        }
        cpa_mbar_arrive_noinc(fullM + 8 * buf);
    };

    float acc[4][4][4];
    #pragma unroll
    for (int a = 0; a < 4; a++)
        #pragma unroll
        for (int b = 0; b < 4; b++)
            #pragma unroll
            for (int c = 0; c < 4; c++) acc[a][b][c] = 0.f;

    auto compute_stage = [&](int S_imm) {
        const uint32_t aOff = (uint32_t)(S_imm * BM * SST * 2);
        const uint32_t bOff = (uint32_t)(S_imm * BN * SST * 2);
        #pragma unroll
        for (int ks = 0; ks < 4; ++ks) {
            uint32_t aa[4][4], bb[2][4];
            #pragma unroll
            for (int mt = 0; mt < 4; ++mt)
                ldsm4(aa[mt], aRow[mt] + aOff + (uint32_t)(ks * 32));
            #pragma unroll
            for (int p = 0; p < 2; ++p)
                ldsm4(bb[p], bRow[p] + bOff + (uint32_t)(ks * 32));
            #pragma unroll
            for (int mt = 0; mt < 4; ++mt)
                #pragma unroll
                for (int p = 0; p < 2; ++p) {
                    mma_f16(acc[mt][2 * p],     aa[mt], &bb[p][0]);
                    mma_f16(acc[mt][2 * p + 1], aa[mt], &bb[p][2]);
                }
        }
    };

    // ---- first tile grab (mailbox slot 0, seq 1) ----
    if (tid == 0) {
        int t0 = atomicAdd(&g_ctr, 1);
        shT[0] = t0;
        __threadfence_block();
        *shSq = 1;
    }
    while (*shSq < 1) {}
    int cur = shT[0];
    int m0 = (cur >> 4) * BM, n0 = (cur & 15) * BN;

    load_tile(m0, n0, 0, 0);
    load_tile(m0, n0, 1, 1);

    int tc = 1;              // next grab sequence
    bool first = true;

    for (;;) {
        // async grab of the next tile (slot tc&1); consumed at j==7 below
        if (tid == 0) {
            int tn = atomicAdd(&g_ctr, 1);
            shT[tc & 1] = tn;
            __threadfence_block();
            *shSq = tc + 1;
        }

        int nxt = NTILES, nm0 = 0, nn0 = 0;
        // 32 ktiles = 8 quads; parity = j&1 for every tile (32 % (2*NSTG) == 0)
        for (int j = 0; j < 8; ++j) {
            const uint32_t pj  = (uint32_t)(j & 1);
            const uint32_t pjm = (uint32_t)((j - 1) & 1);
            // u=0: kt=4j, stage 0
            mbar_wait(fullM + 0, pj);
            compute_stage(0);
            __syncwarp();
            if (lane == 0) mbar_arrive(emptyM + 0);
            if (!(first && j == 0)) mbar_wait(emptyM + 16, pjm);  // stage 2
            load_tile(m0, n0, 4 * j + 2, 2);
            // u=1: stage 1
            mbar_wait(fullM + 8, pj);
            compute_stage(1);
            __syncwarp();
            if (lane == 0) mbar_arrive(emptyM + 8);
            if (!(first && j == 0)) mbar_wait(emptyM + 24, pjm);  // stage 3
            load_tile(m0, n0, 4 * j + 3, 3);
            // u=2: stage 2
            mbar_wait(fullM + 16, pj);
            compute_stage(2);
            __syncwarp();
            if (lane == 0) mbar_arrive(emptyM + 16);
            if (j < 7) {
                mbar_wait(emptyM + 0, pj);                        // stage 0
                load_tile(m0, n0, 4 * j + 4, 0);
            } else {
                // fetch next-tile id; mailbox written a full tile ago
                while (*shSq < tc + 1) {}
                nxt = shT[tc & 1];
                if (nxt < NTILES) {
                    nm0 = (nxt >> 4) * BM; nn0 = (nxt & 15) * BN;
                    mbar_wait(emptyM + 0, pj);
                    load_tile(nm0, nn0, 0, 0);
                }
            }
            // u=3: stage 3
            mbar_wait(fullM + 24, pj);
            compute_stage(3);
            __syncwarp();
            if (lane == 0) mbar_arrive(emptyM + 24);
            if (j < 7) {
                mbar_wait(emptyM + 8, pj);                        // stage 1
                load_tile(m0, n0, 4 * j + 5, 1);
            } else if (nxt < NTILES) {
                mbar_wait(emptyM + 8, pj);
                load_tile(nm0, nn0, 1, 1);
            }
        }

        // ---- epilogue for cur (overlaps next tile's in-flight loads) ----
        const int l4 = lane >> 2, l2 = (lane & 3) * 2;
        #pragma unroll
        for (int mt = 0; mt < 4; ++mt) {
            int mrow = m0 + warp_m + mt * 16 + l4;
            float s0 = g_rs[mrow];
            float s1 = g_rs[mrow + 8];
            #pragma unroll
            for (int nt = 0; nt < 4; ++nt) {
                int n = n0 + warp_n + nt * 8 + l2;
                float be0 = g_beta[n], be1 = g_beta[n + 1];
                float bi0 = bias[n],   bi1 = bias[n + 1];
                float2 r0, r1;
                r0.x = acc[mt][nt][0] * be0 * s0 + bi0;
                r0.y = acc[mt][nt][1] * be1 * s0 + bi1;
                r1.x = acc[mt][nt][2] * be0 * s1 + bi0;
                r1.y = acc[mt][nt][3] * be1 * s1 + bi1;
                *reinterpret_cast<float2*>(out + (size_t)mrow * OUT_F + n) = r0;
                *reinterpret_cast<float2*>(out + (size_t)(mrow + 8) * OUT_F + n) = r1;
                acc[mt][nt][0] = 0.f; acc[mt][nt][1] = 0.f;
                acc[mt][nt][2] = 0.f; acc[mt][nt][3] = 0.f;
            }
        }

        if (nxt >= NTILES) break;
        m0 = nm0; n0 = nn0;
        tc++;
        first = false;
    }
}

// ---------------- launch ----------------------------------------------------
extern "C" void kernel_launch(void* const* d_in, const int* in_sizes, int n_in,
                              void* d_out, int out_size) {
    const float* x    = (const float*)d_in[0];
    const float* wgt  = (const float*)d_in[1];
    const float* bias = (const float*)d_in[2];
    float* out = (float*)d_out;

    prep_kernel<<<2048 + BATCH, 256>>>(x, wgt);

    const int smem = 128 + NSTG * (BM + BN) * SST * (int)sizeof(__half);  // 221312
    cudaFuncSetAttribute(gemm_kernel, cudaFuncAttributeMaxDynamicSharedMemorySize, smem);

    cudaLaunchConfig_t cfg = {};
    cfg.gridDim = dim3(148);              // persistent: one CTA per SM
    cfg.blockDim = dim3(NTHR);
    cfg.dynamicSmemBytes = smem;
    cfg.stream = 0;
    cudaLaunchAttribute attrs[1];
    attrs[0].id = cudaLaunchAttributeProgrammaticStreamSerialization;
    attrs[0].val.programmaticStreamSerializationAllowed = 1;
    cfg.attrs = attrs;
    cfg.numAttrs = 1;
    cudaLaunchKernelEx(&cfg, gemm_kernel, bias, out);
}

// round 17
// speedup vs baseline: 1.0815x; 1.0815x over previous
#include <cuda_runtime.h>
#include <cuda_fp16.h>
#include <cstdint>

#define BATCH 8192
#define IN_F  2048
#define OUT_F 2048
#define QB    7.0f
#define EPSF  1e-5f

// ---------------- scratch (static device arrays; no cudaMalloc) -------------
__device__ __half g_xq[(size_t)BATCH * IN_F];    // 32 MB quantized activations
__device__ __half g_wbin[(size_t)OUT_F * IN_F];  // 8 MB  sign weights
__device__ float  g_beta[OUT_F];
__device__ float  g_rs[BATCH];
__device__ int    g_ctr;                          // persistent-tile counter

// ---------------- fused prep: register-resident rows ------------------------
__global__ __launch_bounds__(256) void prep_kernel(const float* __restrict__ x,
                                                   const float* __restrict__ w) {
    const int tid = threadIdx.x, lane = tid & 31, wid = tid >> 5;
    __shared__ float red[3][8];
    if (blockIdx.x == 0 && tid == 0) g_ctr = 0;   // reset tile counter

    float v[8];
    if (blockIdx.x < 2048) {
        const int o = blockIdx.x;
        const float4* row = (const float4*)(w + (size_t)o * IN_F) + tid * 2;
        float4 p0 = row[0], p1 = row[1];
        v[0]=p0.x; v[1]=p0.y; v[2]=p0.z; v[3]=p0.w;
        v[4]=p1.x; v[5]=p1.y; v[6]=p1.z; v[7]=p1.w;

        float s0 = 0.f, s1 = 0.f;
        #pragma unroll
        for (int i = 0; i < 8; i++) { s0 += v[i]; s1 += fabsf(v[i]); }
        #pragma unroll
        for (int off = 16; off; off >>= 1) {
            s0 += __shfl_xor_sync(0xffffffffu, s0, off);
            s1 += __shfl_xor_sync(0xffffffffu, s1, off);
        }
        if (lane == 0) { red[0][wid] = s0; red[1][wid] = s1; }
        __syncthreads();
        float t0 = 0.f, t1 = 0.f;
        #pragma unroll
        for (int i = 0; i < 8; i++) { t0 += red[0][i]; t1 += red[1][i]; }
        float mean = t0 * (1.0f / IN_F);
        if (tid == 0) g_beta[o] = t1 * (1.0f / IN_F);

        __half h[8];
        #pragma unroll
        for (int i = 0; i < 8; i++) {
            float c = v[i] - mean;
            h[i] = __float2half_rn((c > 0.f) ? 1.0f : ((c < 0.f) ? -1.0f : 0.0f));
        }
        *((uint4*)(g_wbin + (size_t)o * IN_F) + tid) = *(const uint4*)h;
    } else {
        const int b = blockIdx.x - 2048;
        const float4* row = (const float4*)(x + (size_t)b * IN_F) + tid * 2;
        float4 p0 = row[0], p1 = row[1];
        v[0]=p0.x; v[1]=p0.y; v[2]=p0.z; v[3]=p0.w;
        v[4]=p1.x; v[5]=p1.y; v[6]=p1.z; v[7]=p1.w;

        float s0 = 0.f, s1 = 0.f;
        #pragma unroll
        for (int i = 0; i < 8; i++) { s0 += v[i]; s1 += v[i] * v[i]; }
        #pragma unroll
        for (int off = 16; off; off >>= 1) {
            s0 += __shfl_xor_sync(0xffffffffu, s0, off);
            s1 += __shfl_xor_sync(0xffffffffu, s1, off);
        }
        if (lane == 0) { red[0][wid] = s0; red[1][wid] = s1; }
        __syncthreads();
        float t0 = 0.f, t1 = 0.f;
        #pragma unroll
        for (int i = 0; i < 8; i++) { t0 += red[0][i]; t1 += red[1][i]; }
        float mu   = t0 * (1.0f / IN_F);
        float var  = t1 * (1.0f / IN_F) - mu * mu;
        float rstd = rsqrtf(var + EPSF);

        float lm = 0.f;
        #pragma unroll
        for (int i = 0; i < 8; i++) lm = fmaxf(lm, fabsf(v[i] - mu));
        #pragma unroll
        for (int off = 16; off; off >>= 1)
            lm = fmaxf(lm, __shfl_xor_sync(0xffffffffu, lm, off));
        if (lane == 0) red[2][wid] = lm;
        __syncthreads();
        float mx = 0.f;
        #pragma unroll
        for (int i = 0; i < 8; i++) mx = fmaxf(mx, red[2][i]);
        float gama = fmaxf(mx * rstd, EPSF);
        float s = rstd * (QB / gama);
        const float clo = -QB + EPSF, chi = QB - EPSF;

        __half h[8];
        #pragma unroll
        for (int i = 0; i < 8; i++) {
            float q = (v[i] - mu) * s;
            h[i] = __float2half_rn(fminf(fmaxf(q, clo), chi));
        }
        *((uint4*)(g_xq + (size_t)b * IN_F) + tid) = *(const uint4*)h;
        if (tid == 0) g_rs[b] = gama * (1.0f / QB);
    }
    cudaTriggerProgrammaticLaunchCompletion();
}

// ---------------- GEMM: persistent R15 pipeline (128x128, NSTG=3) ----------
#define BM 128
#define BN 128
#define BK 64
#define SST 72            // smem row stride in halves (144B rows, conflict-free)
#define NSTG 3
#define NTHR 256
#define NTILES 1024       // (8192/128) * (2048/128)

__device__ __forceinline__ void mma_f16(float* c, const uint32_t* a, const uint32_t* b) {
    asm volatile(
        "mma.sync.aligned.m16n8k16.row.col.f32.f16.f16.f32 "
        "{%0,%1,%2,%3}, {%4,%5,%6,%7}, {%8,%9}, {%0,%1,%2,%3};\n"
        : "+f"(c[0]), "+f"(c[1]), "+f"(c[2]), "+f"(c[3])
        : "r"(a[0]), "r"(a[1]), "r"(a[2]), "r"(a[3]), "r"(b[0]), "r"(b[1]));
}

__device__ __forceinline__ void ldsm4(uint32_t* r, uint32_t addr) {
    asm volatile("ldmatrix.sync.aligned.m8n8.x4.shared.b16 {%0,%1,%2,%3}, [%4];\n"
                 : "=r"(r[0]), "=r"(r[1]), "=r"(r[2]), "=r"(r[3]) : "r"(addr));
}

__device__ __forceinline__ void cpa16(uint32_t d, const void* s) {
    asm volatile("cp.async.cg.shared.global [%0], [%1], 16;\n" :: "r"(d), "l"(s));
}
__device__ __forceinline__ void mbar_init(uint32_t a, uint32_t cnt) {
    asm volatile("mbarrier.init.shared.b64 [%0], %1;" :: "r"(a), "r"(cnt) : "memory");
}
__device__ __forceinline__ void mbar_arrive(uint32_t a) {
    asm volatile("mbarrier.arrive.shared.b64 _, [%0];" :: "r"(a) : "memory");
}
__device__ __forceinline__ void cpa_mbar_arrive_noinc(uint32_t a) {
    asm volatile("cp.async.mbarrier.arrive.noinc.shared.b64 [%0];" :: "r"(a) : "memory");
}
__device__ __forceinline__ void mbar_wait(uint32_t a, uint32_t parity) {
    asm volatile(
        "{\n\t.reg .pred P;\n\t"
        "LW%=:\n\t"
        "mbarrier.try_wait.parity.acquire.cta.shared::cta.b64 P, [%0], %1, 0x989680;\n\t"
        "@P bra LD%=;\n\t"
        "bra LW%=;\n\t"
        "LD%=:\n\t}"
        :: "r"(a), "r"(parity) : "memory");
}

__global__ __launch_bounds__(NTHR, 2) void gemm_kernel(const float* __restrict__ bias,
                                                       float* __restrict__ out) {
    extern __shared__ __half sm[];
    // bytes [0,24): full[3]; [24,48): empty[3]; [48,52): tile id; tiles @64
    __half* sA = sm + 32;                        // NSTG * BM * SST halves
    __half* sB = sm + 32 + NSTG * BM * SST;      // NSTG * BN * SST halves
    volatile int* shT = (volatile int*)((char*)sm + 48);
    const uint32_t mbarBase = (uint32_t)__cvta_generic_to_shared(sm);
    const uint32_t fullM  = mbarBase;            // + 8*s
    const uint32_t emptyM = mbarBase + 24;       // + 8*s

    const int tid = threadIdx.x;
    const int lane = tid & 31, w = tid >> 5;
    const int wm = w >> 2, wn = w & 3;           // 2x4 warp grid, warp tile 64x32
    const int warp_m = wm * 64, warp_n = wn * 32;

    const uint32_t baseA = (uint32_t)__cvta_generic_to_shared(sA);
    const uint32_t baseB = (uint32_t)__cvta_generic_to_shared(sB);

    const __half* __restrict__ Aq = g_xq;
    const __half* __restrict__ Bw = g_wbin;

    const int matA = lane >> 3, ra = lane & 7;
    const int a_row_off = (matA & 1) * 8 + ra;
    const int a_col_off = (matA >> 1) * 8;
    const int b_n_off   = ((matA >> 1) ? 8 : 0) + ra;
    const int b_k_off   = (matA & 1) * 8;

    uint32_t aRow[4], bRow[2];
    #pragma unroll
    for (int mt = 0; mt < 4; ++mt)
        aRow[mt] = baseA + (uint32_t)((warp_m + mt * 16 + a_row_off) * SST + a_col_off) * 2;
    #pragma unroll
    for (int p = 0; p < 2; ++p)
        bRow[p] = baseB + (uint32_t)((warp_n + p * 16 + b_n_off) * SST + b_k_off) * 2;

    cudaGridDependencySynchronize();

    float acc[4][4][4];
    #pragma unroll
    for (int a = 0; a < 4; a++)
        #pragma unroll
        for (int b = 0; b < 4; b++)
            #pragma unroll
            for (int c = 0; c < 4; c++) acc[a][b][c] = 0.f;

    auto compute_stage = [&](int S_imm) {
        const uint32_t aOff = (uint32_t)(S_imm * BM * SST * 2);
        const uint32_t bOff = (uint32_t)(S_imm * BN * SST * 2);
        #pragma unroll
        for (int ks = 0; ks < 4; ++ks) {
            uint32_t aa[4][4], bb[2][4];
            #pragma unroll
            for (int mt = 0; mt < 4; ++mt)
                ldsm4(aa[mt], aRow[mt] + aOff + (uint32_t)(ks * 32));
            #pragma unroll
            for (int p = 0; p < 2; ++p)
                ldsm4(bb[p], bRow[p] + bOff + (uint32_t)(ks * 32));
            #pragma unroll
            for (int mt = 0; mt < 4; ++mt)
                #pragma unroll
                for (int p = 0; p < 2; ++p) {
                    mma_f16(acc[mt][2 * p],     aa[mt], &bb[p][0]);
                    mma_f16(acc[mt][2 * p + 1], aa[mt], &bb[p][2]);
                }
        }
    };

    // ---------------- persistent tile loop ----------------
    for (;;) {
        // grab a tile + fresh barriers (all parities reset to 0)
        if (tid == 0) {
            shT[0] = atomicAdd(&g_ctr, 1);
            #pragma unroll
            for (int s = 0; s < NSTG; s++) {
                mbar_init(fullM + 8 * s, NTHR);
                mbar_init(emptyM + 8 * s, 8);
            }
        }
        __syncthreads();
        const int cur = shT[0];
        if (cur >= NTILES) break;
        const int m0 = (cur >> 4) * BM;
        const int n0 = (cur & 15) * BN;

        auto load_tile = [&](int kt, int buf) {
            const int k0 = kt * BK;
            #pragma unroll
            for (int i = 0; i < 4; i++) {
                int c = tid + i * NTHR;
                int r = c >> 3, kc = c & 7;
                uint32_t doff = (uint32_t)((buf * BM * SST + r * SST + kc * 8) * 2);
                cpa16(baseA + doff, Aq + (size_t)(m0 + r) * IN_F + k0 + kc * 8);
            }
            #pragma unroll
            for (int i = 0; i < 4; i++) {
                int c = tid + i * NTHR;
                int r = c >> 3, kc = c & 7;
                uint32_t doff = (uint32_t)((buf * BN * SST + r * SST + kc * 8) * 2);
                cpa16(baseB + doff, Bw + (size_t)(n0 + r) * IN_F + k0 + kc * 8);
            }
            cpa_mbar_arrive_noinc(fullM + 8 * buf);
        };

        load_tile(0, 0);
        load_tile(1, 1);

        // KT = 32 = 3*10 + 2: 10 triple iterations, 2-tile tail
        for (int j = 0; j < 10; ++j) {
            const uint32_t pj  = (uint32_t)(j & 1);
            const uint32_t pj1 = (uint32_t)((j - 1) & 1);
            // u=0: kt=3j, stage 0
            mbar_wait(fullM + 0, pj);
            compute_stage(0);
            __syncwarp();
            if (lane == 0) mbar_arrive(emptyM + 0);
            if (j >= 1) mbar_wait(emptyM + 16, pj1);   // stage 2
            load_tile(3 * j + 2, 2);
            // u=1: kt=3j+1, stage 1
            mbar_wait(fullM + 8, pj);
            compute_stage(1);
            __syncwarp();
            if (lane == 0) mbar_arrive(emptyM + 8);
            mbar_wait(emptyM + 0, pj);                 // stage 0
            load_tile(3 * j + 3, 0);
            // u=2: kt=3j+2, stage 2
            mbar_wait(fullM + 16, pj);
            compute_stage(2);
            __syncwarp();
            if (lane == 0) mbar_arrive(emptyM + 16);
            mbar_wait(emptyM + 8, pj);                 // stage 1
            load_tile(3 * j + 4, 1);
        }
        // tail: kt=30 (stage 0, parity 0), kt=31 (stage 1, parity 0)
        mbar_wait(fullM + 0, 0);
        compute_stage(0);
        mbar_wait(fullM + 8, 0);
        compute_stage(1);

        // epilogue: y = acc * beta[n] * rs[m] + bias[n]; reset acc
        const int l4 = lane >> 2, l2 = (lane & 3) * 2;
        #pragma unroll
        for (int mt = 0; mt < 4; ++mt) {
            int mrow = m0 + warp_m + mt * 16 + l4;
            float s0 = g_rs[mrow];
            float s1 = g_rs[mrow + 8];
            #pragma unroll
            for (int nt = 0; nt < 4; ++nt) {
                int n = n0 + warp_n + nt * 8 + l2;
                float be0 = g_beta[n], be1 = g_beta[n + 1];
                float bi0 = bias[n],   bi1 = bias[n + 1];
                float2 r0, r1;
                r0.x = acc[mt][nt][0] * be0 * s0 + bi0;
                r0.y = acc[mt][nt][1] * be1 * s0 + bi1;
                r1.x = acc[mt][nt][2] * be0 * s1 + bi0;
                r1.y = acc[mt][nt][3] * be1 * s1 + bi1;
                *reinterpret_cast<float2*>(out + (size_t)mrow * OUT_F + n) = r0;
                *reinterpret_cast<float2*>(out + (size_t)(mrow + 8) * OUT_F + n) = r1;
                acc[mt][nt][0] = 0.f; acc[mt][nt][1] = 0.f;
                acc[mt][nt][2] = 0.f; acc[mt][nt][3] = 0.f;
            }
        }
        __syncthreads();   // all warps done with barriers before re-init
    }
}

// ---------------- launch ----------------------------------------------------
extern "C" void kernel_launch(void* const* d_in, const int* in_sizes, int n_in,
                              void* d_out, int out_size) {
    const float* x    = (const float*)d_in[0];
    const float* wgt  = (const float*)d_in[1];
    const float* bias = (const float*)d_in[2];
    float* out = (float*)d_out;

    prep_kernel<<<2048 + BATCH, 256>>>(x, wgt);

    const int smem = 64 + NSTG * (BM + BN) * SST * (int)sizeof(__half);  // 110656
    cudaFuncSetAttribute(gemm_kernel, cudaFuncAttributeMaxDynamicSharedMemorySize, smem);

    cudaLaunchConfig_t cfg = {};
    cfg.gridDim = dim3(296);              // persistent: 2 CTAs per SM
    cfg.blockDim = dim3(NTHR);
    cfg.dynamicSmemBytes = smem;
    cfg.stream = 0;
    cudaLaunchAttribute attrs[1];
    attrs[0].id = cudaLaunchAttributeProgrammaticStreamSerialization;
    attrs[0].val.programmaticStreamSerializationAllowed = 1;
    cfg.attrs = attrs;
    cfg.numAttrs = 1;
    cudaLaunchKernelEx(&cfg, gemm_kernel, bias, out);
}